// round 1
// baseline (speedup 1.0000x reference)
#include <cuda_runtime.h>
#include <cstdio>

#define B_  4
#define C_  256
#define C8_ 32
#define HH  64
#define WW  64
#define NN  4096   // H*W

// ---- scratch (static device globals; no allocation allowed) ----
__device__ float g_q[B_ * C8_ * NN];   // [b][d][n]   2 MB
__device__ float g_k[B_ * C8_ * NN];   // [b][d][n]   2 MB
__device__ float g_v[(size_t)B_ * NN * C_];  // [b][n][c]  16 MB

// ============================================================================
// Kernel 1: fused q (1x3 conv, pad W) + k (3x1 conv, pad H) projections.
// One CTA per (b, h): loads x rows h-1, h, h+1 for all 256 channels into smem,
// each thread produces 8 w-positions for one of 32 output dims (q and k).
// ============================================================================
__global__ __launch_bounds__(256) void qk_conv_kernel(
    const float* __restrict__ x,
    const float* __restrict__ Wq, const float* __restrict__ bq,
    const float* __restrict__ Wk, const float* __restrict__ bk)
{
    extern __shared__ float xs[];          // [3][256][64] = 192 KB
    const int b = blockIdx.x >> 6;
    const int h = blockIdx.x & 63;
    const int t = threadIdx.x;

    for (int r = 0; r < 3; r++) {
        const int hh = h - 1 + r;
        for (int idx = t; idx < C_ * WW; idx += 256) {
            const int c = idx >> 6, w = idx & 63;
            float v = 0.f;
            if (hh >= 0 && hh < HH)
                v = x[((size_t)(b * C_ + c) * HH + hh) * WW + w];
            xs[(r * C_ + c) * WW + w] = v;
        }
    }
    __syncthreads();

    const int d  = t >> 3;          // 0..31
    const int w0 = (t & 7) << 3;    // 0,8,...,56
    float qa[8], ka[8];
    const float bqd = bq[d], bkd = bk[d];
#pragma unroll
    for (int u = 0; u < 8; u++) { qa[u] = bqd; ka[u] = bkd; }

    const float* wqp = Wq + d * C_ * 3;   // [O,I,1,3]
    const float* wkp = Wk + d * C_ * 3;   // [O,I,3,1]
    for (int c = 0; c < C_; c++) {
        const float wq0 = wqp[c * 3 + 0], wq1 = wqp[c * 3 + 1], wq2 = wqp[c * 3 + 2];
        const float wk0 = wkp[c * 3 + 0], wk1 = wkp[c * 3 + 1], wk2 = wkp[c * 3 + 2];
        const float* x0 = &xs[(0 * C_ + c) * WW];
        const float* x1 = &xs[(1 * C_ + c) * WW];
        const float* x2 = &xs[(2 * C_ + c) * WW];
#pragma unroll
        for (int u = 0; u < 8; u++) {
            const int w = w0 + u;
            const float xm = (w > 0)  ? x1[w - 1] : 0.f;
            const float xc = x1[w];
            const float xp = (w < 63) ? x1[w + 1] : 0.f;
            qa[u] += wq0 * xm + wq1 * xc + wq2 * xp;
            ka[u] += wk0 * x0[w] + wk1 * xc + wk2 * x2[w];
        }
    }
    const size_t base = ((size_t)(b * C8_ + d)) * NN + h * WW + w0;
#pragma unroll
    for (int u = 0; u < 8; u++) { g_q[base + u] = qa[u]; g_k[base + u] = ka[u]; }
}

// ============================================================================
// Kernel 2: v = Wv(256x256) @ x + bv, written as g_v[b][n][c] so the attention
// kernel can load v tiles with fully coalesced, conflict-free float4s.
// CTA tile: 128 n x 64 c, K=256 in chunks of 32. 256 thr, 4n x 8c per thread.
// ============================================================================
__global__ __launch_bounds__(256) void v_gemm_kernel(
    const float* __restrict__ x, const float* __restrict__ Wv,
    const float* __restrict__ bv)
{
    __shared__ float Wt[32 * 68];    // [k][c] transposed, padded
    __shared__ float Xs[32 * 128];   // [k][n]
    const int n0  = blockIdx.x * 128;
    const int c0b = blockIdx.y * 64;
    const int b   = blockIdx.z;
    const int t   = threadIdx.x;
    const int n0t = (t >> 3) * 4;
    const int c0t = (t & 7) * 8;

    float acc[4][8];
#pragma unroll
    for (int i = 0; i < 4; i++)
#pragma unroll
        for (int j = 0; j < 8; j++) acc[i][j] = 0.f;

    for (int kk = 0; kk < C_; kk += 32) {
        __syncthreads();
#pragma unroll
        for (int r = 0; r < 4; r++) {                     // Xs: 1024 float4s
            const int idx4 = t + r * 256;
            const int row = idx4 >> 5, nq = (idx4 & 31) << 2;
            *(float4*)&Xs[row * 128 + nq] =
                *(const float4*)&x[((size_t)(b * C_ + kk + row)) * NN + n0 + nq];
        }
#pragma unroll
        for (int r = 0; r < 8; r++) {                     // Wt: 2048 floats
            const int idx = t + r * 256;
            const int c = idx >> 5, k = idx & 31;
            Wt[k * 68 + c] = Wv[(size_t)(c0b + c) * C_ + kk + k];
        }
        __syncthreads();
#pragma unroll
        for (int k = 0; k < 32; k++) {
            const float4 xv = *(const float4*)&Xs[k * 128 + n0t];
            const float4 wa = *(const float4*)&Wt[k * 68 + c0t];
            const float4 wb = *(const float4*)&Wt[k * 68 + c0t + 4];
            const float xr[4] = {xv.x, xv.y, xv.z, xv.w};
            const float wr[8] = {wa.x, wa.y, wa.z, wa.w, wb.x, wb.y, wb.z, wb.w};
#pragma unroll
            for (int i = 0; i < 4; i++)
#pragma unroll
                for (int j = 0; j < 8; j++) acc[i][j] += xr[i] * wr[j];
        }
    }
#pragma unroll
    for (int i = 0; i < 4; i++) {
        const int n = n0 + n0t + i;
#pragma unroll
        for (int j = 0; j < 8; j++) {
            const int c = c0b + c0t + j;
            g_v[((size_t)b * NN + n) * C_ + c] = acc[i][j] + bv[c];
        }
    }
}

// ============================================================================
// Kernel 3: flash attention, fp32.
// CTA = (b, 128-query block). Loop j-tiles of 64.
// smem: qs[32][132], ks[32][72], S[64][132] (transposed [j][i]), vs[64][256],
//       alpha[128]. Thread owns 4 queries x 32 channels (strided by 32).
// ============================================================================
#define QS_OFF 0
#define KS_OFF 4224          // 32*132
#define SS_OFF 6528          // + 32*72
#define VS_OFF 14976         // + 64*132
#define AL_OFF 31360         // + 64*256
#define SM_FLOATS 31488      // + 128   -> 125952 bytes

__global__ __launch_bounds__(256, 1) void attn_kernel(float* __restrict__ out)
{
    extern __shared__ float sm[];
    float* qs  = sm + QS_OFF;   // [d][i] stride 132
    float* ks  = sm + KS_OFF;   // [d][j] stride 72
    float* Ssm = sm + SS_OFF;   // [j][i] stride 132
    float* vs  = sm + VS_OFF;   // [j][c] stride 256
    float* al  = sm + AL_OFF;   // [128]

    const int t   = threadIdx.x;
    const int b   = blockIdx.y;
    const int i0g = blockIdx.x * 128;
    const int i0  = (t >> 3) * 4;   // query group
    const int j0  = (t & 7) * 8;    // key group (QK phase)
    const int c0  = (t & 7) * 4;    // channel base (PV phase, strided by 32)

    {   // load q tile [32][128]
        const float* qsrc = g_q + (size_t)b * C8_ * NN + i0g;
        for (int idx = t; idx < 32 * 128; idx += 256) {
            const int d = idx >> 7, i = idx & 127;
            qs[d * 132 + i] = qsrc[(size_t)d * NN + i];
        }
    }

    float acc[128];
#pragma unroll
    for (int a = 0; a < 128; a++) acc[a] = 0.f;
    float m_i = -1e30f, l_i = 0.f;

    for (int jt = 0; jt < 64; jt++) {
        const int jg = jt * 64;
        __syncthreads();   // protect ks/vs/S from previous iteration's readers
        {   // k tile [32][64]
            const float* ksrc = g_k + (size_t)b * C8_ * NN + jg;
            for (int idx = t; idx < 32 * 64; idx += 256) {
                const int d = idx >> 6, j = idx & 63;
                ks[d * 72 + j] = ksrc[(size_t)d * NN + j];
            }
        }
        {   // v tile [64][256] — contiguous copy thanks to [b][n][c] layout
            const float4* vsrc = (const float4*)(g_v + ((size_t)b * NN + jg) * C_);
            float4* vdst = (float4*)vs;
            for (int idx = t; idx < 64 * 64; idx += 256) vdst[idx] = vsrc[idx];
        }
        __syncthreads();

        {   // QK: S[j][i] for 8 j x 4 i per thread
            float s[32];
#pragma unroll
            for (int a = 0; a < 32; a++) s[a] = 0.f;
#pragma unroll 8
            for (int d = 0; d < 32; d++) {
                const float4 q4  = *(const float4*)&qs[d * 132 + i0];
                const float4 ka4 = *(const float4*)&ks[d * 72 + j0];
                const float4 kb4 = *(const float4*)&ks[d * 72 + j0 + 4];
                const float qr[4] = {q4.x, q4.y, q4.z, q4.w};
                const float kr[8] = {ka4.x, ka4.y, ka4.z, ka4.w,
                                     kb4.x, kb4.y, kb4.z, kb4.w};
#pragma unroll
                for (int jj = 0; jj < 8; jj++)
#pragma unroll
                    for (int ii = 0; ii < 4; ii++)
                        s[jj * 4 + ii] += kr[jj] * qr[ii];
            }
#pragma unroll
            for (int jj = 0; jj < 8; jj++)
                *(float4*)&Ssm[(j0 + jj) * 132 + i0] =
                    make_float4(s[jj * 4 + 0], s[jj * 4 + 1], s[jj * 4 + 2], s[jj * 4 + 3]);
        }
        __syncthreads();

        // online softmax: thread i (< 128) owns row i
        if (t < 128) {
            float mx = -1e30f;
#pragma unroll 8
            for (int j = 0; j < 64; j++) mx = fmaxf(mx, Ssm[j * 132 + t]);
            const float mn = fmaxf(m_i, mx);
            const float a  = __expf(m_i - mn);
            float sum = 0.f;
#pragma unroll 8
            for (int j = 0; j < 64; j++) {
                const float p = __expf(Ssm[j * 132 + t] - mn);
                Ssm[j * 132 + t] = p;
                sum += p;
            }
            l_i = l_i * a + sum;
            m_i = mn;
            al[t] = a;
        }
        __syncthreads();

        {   // rescale + PV accumulate
            const float a0 = al[i0], a1 = al[i0 + 1], a2 = al[i0 + 2], a3 = al[i0 + 3];
#pragma unroll
            for (int k2 = 0; k2 < 32; k2++) {
                acc[0 * 32 + k2] *= a0; acc[1 * 32 + k2] *= a1;
                acc[2 * 32 + k2] *= a2; acc[3 * 32 + k2] *= a3;
            }
            for (int j = 0; j < 64; j++) {
                const float4 p4 = *(const float4*)&Ssm[j * 132 + i0];
                const float pr[4] = {p4.x, p4.y, p4.z, p4.w};
                const float* vrow = &vs[j * 256 + c0];
#pragma unroll
                for (int cc = 0; cc < 8; cc++) {
                    const float4 v4 = *(const float4*)&vrow[cc * 32];
                    const float vr[4] = {v4.x, v4.y, v4.z, v4.w};
#pragma unroll
                    for (int ii = 0; ii < 4; ii++)
#pragma unroll
                        for (int q = 0; q < 4; q++)
                            acc[ii * 32 + cc * 4 + q] += pr[ii] * vr[q];
                }
            }
        }
    }

    __syncthreads();
    if (t < 128) al[t] = 1.f / l_i;
    __syncthreads();
    {
        const float l0 = al[i0], l1 = al[i0 + 1], l2 = al[i0 + 2], l3 = al[i0 + 3];
#pragma unroll
        for (int cc = 0; cc < 8; cc++)
#pragma unroll
            for (int q = 0; q < 4; q++) {
                const int c = c0 + cc * 32 + q;
                float4 o;
                o.x = acc[0 * 32 + cc * 4 + q] * l0;
                o.y = acc[1 * 32 + cc * 4 + q] * l1;
                o.z = acc[2 * 32 + cc * 4 + q] * l2;
                o.w = acc[3 * 32 + cc * 4 + q] * l3;
                *(float4*)&out[((size_t)(b * C_ + c)) * NN + i0g + i0] = o;
            }
    }
}

// ============================================================================
extern "C" void kernel_launch(void* const* d_in, const int* in_sizes, int n_in,
                              void* d_out, int out_size)
{
    const float* x  = (const float*)d_in[0];
    const float* Wq = (const float*)d_in[1];
    const float* bq = (const float*)d_in[2];
    const float* Wk = (const float*)d_in[3];
    const float* bk = (const float*)d_in[4];
    const float* Wv = (const float*)d_in[5];
    const float* bv = (const float*)d_in[6];
    float* out = (float*)d_out;

    // opt-in smem sizes (idempotent, host-side, capture-safe)
    cudaFuncSetAttribute(qk_conv_kernel, cudaFuncAttributeMaxDynamicSharedMemorySize,
                         3 * C_ * WW * (int)sizeof(float));          // 192 KB
    cudaFuncSetAttribute(attn_kernel, cudaFuncAttributeMaxDynamicSharedMemorySize,
                         SM_FLOATS * (int)sizeof(float));            // ~123 KB

    qk_conv_kernel<<<B_ * HH, 256, 3 * C_ * WW * sizeof(float)>>>(x, Wq, bq, Wk, bk);
    v_gemm_kernel<<<dim3(NN / 128, C_ / 64, B_), 256>>>(x, Wv, bv);
    attn_kernel<<<dim3(NN / 128, B_), 256, SM_FLOATS * sizeof(float)>>>(out);
}

// round 3
// speedup vs baseline: 1.1494x; 1.1494x over previous
#include <cuda_runtime.h>

#define B_  4
#define C_  256
#define C8_ 32
#define HH  64
#define WW  64
#define NN  4096   // H*W

// ---- scratch (static device globals; no allocation allowed) ----
__device__ float g_q[B_ * C8_ * NN];          // [b][d][n]
__device__ float g_k[B_ * C8_ * NN];          // [b][d][n]
__device__ float g_v[(size_t)B_ * NN * C_];   // [b][n][c]

// ---- packed f32x2 helpers (sm_100+: doubles fp32 FMA throughput).
// NOTE: must use b64 ("l") operands, not f64 ("d") — ptxas rejects %fd here.
typedef unsigned long long u64;
__device__ __forceinline__ u64 ffma2(u64 a, u64 b, u64 c) {
    u64 r; asm("fma.rn.f32x2 %0, %1, %2, %3;" : "=l"(r) : "l"(a), "l"(b), "l"(c));
    return r;
}
__device__ __forceinline__ u64 fmul2(u64 a, u64 b) {
    u64 r; asm("mul.rn.f32x2 %0, %1, %2;" : "=l"(r) : "l"(a), "l"(b));
    return r;
}
__device__ __forceinline__ u64 dup2(float v) {
    u64 r; asm("mov.b64 %0, {%1, %1};" : "=l"(r) : "f"(v));
    return r;
}
__device__ __forceinline__ float2 unpk(u64 d) {
    float2 r; asm("mov.b64 {%0, %1}, %2;" : "=f"(r.x), "=f"(r.y) : "l"(d));
    return r;
}

// ============================================================================
// Kernel 1: q (1x3 conv) + k (3x1 conv).  grid (half, h, b) = (2, 64, 4).
// CTA computes 16 q-dims + 16 k-dims for one (b,h) row, chunking C by 64.
// smem: xs[3][64][64] (48KB) + staged weights (24KB) => occupancy 3.
// ============================================================================
__global__ __launch_bounds__(256) void qk_conv_kernel(
    const float* __restrict__ x,
    const float* __restrict__ Wq, const float* __restrict__ bq,
    const float* __restrict__ Wk, const float* __restrict__ bk)
{
    extern __shared__ float smqk[];
    float* xs = smqk;                 // [3][64][64]
    float* ws = smqk + 3 * 64 * 64;   // [2][16][192]  (q-then-k, [dim][c*3+tap])

    const int b    = blockIdx.z;
    const int h    = blockIdx.y;
    const int half = blockIdx.x;
    const int t    = threadIdx.x;
    const int g    = t >> 3;            // 0..31
    const int w0   = (t & 7) * 8;
    const bool isq = (g < 16);
    const int dl   = isq ? g : (g - 16);
    const int dg   = half * 16 + dl;    // global output dim 0..31

    float a8[8];
#pragma unroll
    for (int u = 0; u < 8; u++) a8[u] = 0.f;

    for (int cb = 0; cb < C_; cb += 64) {
        __syncthreads();
        // x rows h-1,h,h+1 for channels cb..cb+63  (3072 float4s)
        for (int idx = t; idx < 3 * 64 * 16; idx += 256) {
            const int r = idx >> 10, rem = idx & 1023;
            const int c = rem >> 4, wq = (rem & 15) << 2;
            const int hh = h - 1 + r;
            float4 v = make_float4(0.f, 0.f, 0.f, 0.f);
            if (hh >= 0 && hh < HH)
                v = *(const float4*)&x[((size_t)(b * C_ + cb + c) * HH + hh) * WW + wq];
            *(float4*)&xs[(r * 64 + c) * 64 + wq] = v;
        }
        // weights for this chunk: 2 * 16 dims * 192 floats (1536 float4s)
        for (int idx = t; idx < 2 * 16 * 48; idx += 256) {
            const int which = idx / 768, rem = idx - which * 768;
            const int dd = rem / 48, cq = (rem % 48) * 4;
            const float* Wsrc = which ? Wk : Wq;
            *(float4*)&ws[(which * 16 + dd) * 192 + cq] =
                *(const float4*)&Wsrc[(size_t)(half * 16 + dd) * 768 + cb * 3 + cq];
        }
        __syncthreads();

        const float* wrow = &ws[(isq ? dl : 16 + dl) * 192];
        if (isq) {
            for (int c = 0; c < 64; c++) {
                const float wf0 = wrow[c * 3 + 0], wf1 = wrow[c * 3 + 1], wf2 = wrow[c * 3 + 2];
                const float* x1 = &xs[(64 + c) * 64];
                float xr[10];
                xr[0] = (w0 == 0) ? 0.f : x1[w0 - 1];
                const float4 A = *(const float4*)&x1[w0];
                const float4 Bq = *(const float4*)&x1[w0 + 4];
                xr[1] = A.x; xr[2] = A.y; xr[3] = A.z; xr[4] = A.w;
                xr[5] = Bq.x; xr[6] = Bq.y; xr[7] = Bq.z; xr[8] = Bq.w;
                xr[9] = (w0 == 56) ? 0.f : x1[w0 + 8];
#pragma unroll
                for (int u = 0; u < 8; u++)
                    a8[u] += wf0 * xr[u] + wf1 * xr[u + 1] + wf2 * xr[u + 2];
            }
        } else {
            for (int c = 0; c < 64; c++) {
                const float wf0 = wrow[c * 3 + 0], wf1 = wrow[c * 3 + 1], wf2 = wrow[c * 3 + 2];
                const float4 r0a = *(const float4*)&xs[(0 * 64 + c) * 64 + w0];
                const float4 r0b = *(const float4*)&xs[(0 * 64 + c) * 64 + w0 + 4];
                const float4 r1a = *(const float4*)&xs[(1 * 64 + c) * 64 + w0];
                const float4 r1b = *(const float4*)&xs[(1 * 64 + c) * 64 + w0 + 4];
                const float4 r2a = *(const float4*)&xs[(2 * 64 + c) * 64 + w0];
                const float4 r2b = *(const float4*)&xs[(2 * 64 + c) * 64 + w0 + 4];
                const float r0[8] = {r0a.x, r0a.y, r0a.z, r0a.w, r0b.x, r0b.y, r0b.z, r0b.w};
                const float r1[8] = {r1a.x, r1a.y, r1a.z, r1a.w, r1b.x, r1b.y, r1b.z, r1b.w};
                const float r2[8] = {r2a.x, r2a.y, r2a.z, r2a.w, r2b.x, r2b.y, r2b.z, r2b.w};
#pragma unroll
                for (int u = 0; u < 8; u++)
                    a8[u] += wf0 * r0[u] + wf1 * r1[u] + wf2 * r2[u];
            }
        }
    }

    const float bias = isq ? bq[dg] : bk[dg];
    float* dst = isq ? g_q : g_k;
    const size_t base = ((size_t)(b * C8_ + dg)) * NN + h * WW + w0;
#pragma unroll
    for (int u = 0; u < 8; u++) dst[base + u] = a8[u] + bias;
}

// ============================================================================
// Kernel 2: v = Wv @ x + bv, written [b][n][c].  f32x2 inner loop.
// ============================================================================
__global__ __launch_bounds__(256) void v_gemm_kernel(
    const float* __restrict__ x, const float* __restrict__ Wv,
    const float* __restrict__ bv)
{
    __shared__ __align__(16) float Wt[32 * 68];    // [k][c]
    __shared__ __align__(16) float Xs[32 * 128];   // [k][n]
    const int n0  = blockIdx.x * 128;
    const int c0b = blockIdx.y * 64;
    const int b   = blockIdx.z;
    const int t   = threadIdx.x;
    const int n0t = (t >> 3) * 4;
    const int c0t = (t & 7) * 8;

    u64 acc2[4][4];   // [i][c-pair]
#pragma unroll
    for (int i = 0; i < 4; i++)
#pragma unroll
        for (int j = 0; j < 4; j++) acc2[i][j] = 0ull;

    for (int kk = 0; kk < C_; kk += 32) {
        __syncthreads();
#pragma unroll
        for (int r = 0; r < 4; r++) {
            const int idx4 = t + r * 256;
            const int row = idx4 >> 5, nq = (idx4 & 31) << 2;
            *(float4*)&Xs[row * 128 + nq] =
                *(const float4*)&x[((size_t)(b * C_ + kk + row)) * NN + n0 + nq];
        }
#pragma unroll
        for (int r = 0; r < 8; r++) {
            const int idx = t + r * 256;
            const int c = idx >> 5, k = idx & 31;
            Wt[k * 68 + c] = Wv[(size_t)(c0b + c) * C_ + kk + k];
        }
        __syncthreads();
#pragma unroll 8
        for (int k = 0; k < 32; k++) {
            const float4 xv = *(const float4*)&Xs[k * 128 + n0t];
            const ulonglong2 wA = *(const ulonglong2*)&Wt[k * 68 + c0t];
            const ulonglong2 wB = *(const ulonglong2*)&Wt[k * 68 + c0t + 4];
            const u64 xd0 = dup2(xv.x), xd1 = dup2(xv.y), xd2 = dup2(xv.z), xd3 = dup2(xv.w);
            acc2[0][0] = ffma2(xd0, wA.x, acc2[0][0]); acc2[0][1] = ffma2(xd0, wA.y, acc2[0][1]);
            acc2[0][2] = ffma2(xd0, wB.x, acc2[0][2]); acc2[0][3] = ffma2(xd0, wB.y, acc2[0][3]);
            acc2[1][0] = ffma2(xd1, wA.x, acc2[1][0]); acc2[1][1] = ffma2(xd1, wA.y, acc2[1][1]);
            acc2[1][2] = ffma2(xd1, wB.x, acc2[1][2]); acc2[1][3] = ffma2(xd1, wB.y, acc2[1][3]);
            acc2[2][0] = ffma2(xd2, wA.x, acc2[2][0]); acc2[2][1] = ffma2(xd2, wA.y, acc2[2][1]);
            acc2[2][2] = ffma2(xd2, wB.x, acc2[2][2]); acc2[2][3] = ffma2(xd2, wB.y, acc2[2][3]);
            acc2[3][0] = ffma2(xd3, wA.x, acc2[3][0]); acc2[3][1] = ffma2(xd3, wA.y, acc2[3][1]);
            acc2[3][2] = ffma2(xd3, wB.x, acc2[3][2]); acc2[3][3] = ffma2(xd3, wB.y, acc2[3][3]);
        }
    }
#pragma unroll
    for (int i = 0; i < 4; i++) {
        const int n = n0 + n0t + i;
#pragma unroll
        for (int jp = 0; jp < 4; jp++) {
            const float2 f = unpk(acc2[i][jp]);
            const int c = c0b + c0t + 2 * jp;
            g_v[((size_t)b * NN + n) * C_ + c]     = f.x + bv[c];
            g_v[((size_t)b * NN + n) * C_ + c + 1] = f.y + bv[c + 1];
        }
    }
}

// ============================================================================
// Kernel 3: flash attention, fp32 via f32x2 packed FMA.
// CTA = (b, 64-query block).  grid (64, 4) = 256 CTAs, 2 CTAs/SM.
// smem: qs[32][68], ks[32][72], S[64][72] ([j][i]), vs[64][256], al[64].
// ============================================================================
#define AQS 0
#define AKS 2176            // 32*68
#define ASS 4480            // + 32*72
#define AVS 9088            // + 64*72
#define AAL 25472           // + 64*256
#define ATOT 25536          // + 64   -> 102144 bytes

__global__ __launch_bounds__(256, 2) void attn_kernel(float* __restrict__ out)
{
    extern __shared__ __align__(16) float sm[];
    float* qs  = sm + AQS;   // [d][i] stride 68
    float* ks  = sm + AKS;   // [d][j] stride 72
    float* Ssm = sm + ASS;   // [j][i] stride 72
    float* vs  = sm + AVS;   // [j][c] stride 256
    float* al  = sm + AAL;   // [64]

    const int t  = threadIdx.x;
    const int b  = blockIdx.y;
    const int ig = blockIdx.x * 64;

    const int tq = t & 15, tj = t >> 4;
    const int i0  = tq * 4;           // QK: i group
    const int j0  = tj * 4;           // QK: j group
    const int iv0 = tj * 4;           // PV: i group
    const int cv0 = tq * 4;           // PV: c base (strided by 64)
    const int row = t >> 2, part = t & 3;   // softmax: 4 threads/row

    {   // q tile [32][64]
        const float* qsrc = g_q + (size_t)b * C8_ * NN + ig;
        for (int idx = t; idx < 32 * 64; idx += 256) {
            const int d = idx >> 6, i = idx & 63;
            qs[d * 68 + i] = qsrc[(size_t)d * NN + i];
        }
    }

    u64 acc2[4][4][2];   // [ii][cc][c-pair]
#pragma unroll
    for (int a = 0; a < 4; a++)
#pragma unroll
        for (int c = 0; c < 4; c++) { acc2[a][c][0] = 0ull; acc2[a][c][1] = 0ull; }
    float m_i = -1e30f, l_i = 0.f;

    for (int jt = 0; jt < 64; jt++) {
        const int jg = jt * 64;
        __syncthreads();
        {   // k tile [32][64]
            const float* ksrc = g_k + (size_t)b * C8_ * NN + jg;
            for (int idx = t; idx < 32 * 64; idx += 256) {
                const int d = idx >> 6, j = idx & 63;
                ks[d * 72 + j] = ksrc[(size_t)d * NN + j];
            }
        }
        {   // v tile [64][256]
            const float4* vsrc = (const float4*)(g_v + ((size_t)b * NN + jg) * C_);
            float4* vdst = (float4*)vs;
            for (int idx = t; idx < 4096; idx += 256) vdst[idx] = vsrc[idx];
        }
        __syncthreads();

        {   // QK: 4 i x 4 j per thread, packed along j
            u64 s2[4][2];
#pragma unroll
            for (int a = 0; a < 4; a++) { s2[a][0] = 0ull; s2[a][1] = 0ull; }
#pragma unroll 8
            for (int d = 0; d < 32; d++) {
                const float4     q4 = *(const float4*)&qs[d * 68 + i0];
                const ulonglong2 k2 = *(const ulonglong2*)&ks[d * 72 + j0];
                const u64 qd0 = dup2(q4.x), qd1 = dup2(q4.y);
                const u64 qd2 = dup2(q4.z), qd3 = dup2(q4.w);
                s2[0][0] = ffma2(qd0, k2.x, s2[0][0]); s2[0][1] = ffma2(qd0, k2.y, s2[0][1]);
                s2[1][0] = ffma2(qd1, k2.x, s2[1][0]); s2[1][1] = ffma2(qd1, k2.y, s2[1][1]);
                s2[2][0] = ffma2(qd2, k2.x, s2[2][0]); s2[2][1] = ffma2(qd2, k2.y, s2[2][1]);
                s2[3][0] = ffma2(qd3, k2.x, s2[3][0]); s2[3][1] = ffma2(qd3, k2.y, s2[3][1]);
            }
#pragma unroll
            for (int jp = 0; jp < 2; jp++) {
                const float2 a0 = unpk(s2[0][jp]), a1 = unpk(s2[1][jp]);
                const float2 a2 = unpk(s2[2][jp]), a3 = unpk(s2[3][jp]);
                *(float4*)&Ssm[(j0 + 2 * jp) * 72 + i0] =
                    make_float4(a0.x, a1.x, a2.x, a3.x);
                *(float4*)&Ssm[(j0 + 2 * jp + 1) * 72 + i0] =
                    make_float4(a0.y, a1.y, a2.y, a3.y);
            }
        }
        __syncthreads();

        {   // online softmax: 4 threads per row, 16 j each (j = part + jj*4)
            float mx = -1e30f;
#pragma unroll
            for (int jj = 0; jj < 16; jj++)
                mx = fmaxf(mx, Ssm[(part + jj * 4) * 72 + row]);
            mx = fmaxf(mx, __shfl_xor_sync(0xffffffffu, mx, 1));
            mx = fmaxf(mx, __shfl_xor_sync(0xffffffffu, mx, 2));
            const float mn = fmaxf(m_i, mx);
            const float aold = __expf(m_i - mn);
            float sum = 0.f;
#pragma unroll
            for (int jj = 0; jj < 16; jj++) {
                float* p = &Ssm[(part + jj * 4) * 72 + row];
                const float e = __expf(*p - mn);
                *p = e;
                sum += e;
            }
            sum += __shfl_xor_sync(0xffffffffu, sum, 1);
            sum += __shfl_xor_sync(0xffffffffu, sum, 2);
            l_i = l_i * aold + sum;
            m_i = mn;
            if (part == 0) al[row] = aold;
        }
        __syncthreads();

        {   // rescale + PV, packed along c
            const u64 a0 = dup2(al[iv0]),     a1 = dup2(al[iv0 + 1]);
            const u64 a2 = dup2(al[iv0 + 2]), a3 = dup2(al[iv0 + 3]);
#pragma unroll
            for (int cc = 0; cc < 4; cc++) {
                acc2[0][cc][0] = fmul2(acc2[0][cc][0], a0); acc2[0][cc][1] = fmul2(acc2[0][cc][1], a0);
                acc2[1][cc][0] = fmul2(acc2[1][cc][0], a1); acc2[1][cc][1] = fmul2(acc2[1][cc][1], a1);
                acc2[2][cc][0] = fmul2(acc2[2][cc][0], a2); acc2[2][cc][1] = fmul2(acc2[2][cc][1], a2);
                acc2[3][cc][0] = fmul2(acc2[3][cc][0], a3); acc2[3][cc][1] = fmul2(acc2[3][cc][1], a3);
            }
#pragma unroll 4
            for (int j = 0; j < 64; j++) {
                const float4 p4 = *(const float4*)&Ssm[j * 72 + iv0];
                const u64 p0 = dup2(p4.x), p1 = dup2(p4.y);
                const u64 p2 = dup2(p4.z), p3 = dup2(p4.w);
                const float* vrow = &vs[j * 256 + cv0];
#pragma unroll
                for (int cc = 0; cc < 4; cc++) {
                    const ulonglong2 v2 = *(const ulonglong2*)&vrow[cc * 64];
                    acc2[0][cc][0] = ffma2(p0, v2.x, acc2[0][cc][0]);
                    acc2[0][cc][1] = ffma2(p0, v2.y, acc2[0][cc][1]);
                    acc2[1][cc][0] = ffma2(p1, v2.x, acc2[1][cc][0]);
                    acc2[1][cc][1] = ffma2(p1, v2.y, acc2[1][cc][1]);
                    acc2[2][cc][0] = ffma2(p2, v2.x, acc2[2][cc][0]);
                    acc2[2][cc][1] = ffma2(p2, v2.y, acc2[2][cc][1]);
                    acc2[3][cc][0] = ffma2(p3, v2.x, acc2[3][cc][0]);
                    acc2[3][cc][1] = ffma2(p3, v2.y, acc2[3][cc][1]);
                }
            }
        }
    }

    __syncthreads();
    if (part == 0) al[row] = 1.f / l_i;
    __syncthreads();
    {
        const float l0 = al[iv0], l1 = al[iv0 + 1], l2 = al[iv0 + 2], l3 = al[iv0 + 3];
#pragma unroll
        for (int cc = 0; cc < 4; cc++)
#pragma unroll
            for (int cp = 0; cp < 2; cp++) {
                const float2 x0 = unpk(acc2[0][cc][cp]);
                const float2 x1 = unpk(acc2[1][cc][cp]);
                const float2 x2 = unpk(acc2[2][cc][cp]);
                const float2 x3 = unpk(acc2[3][cc][cp]);
                const int c = cv0 + cc * 64 + cp * 2;
                const float4 oA = make_float4(x0.x * l0, x1.x * l1, x2.x * l2, x3.x * l3);
                const float4 oB = make_float4(x0.y * l0, x1.y * l1, x2.y * l2, x3.y * l3);
                *(float4*)&out[((size_t)(b * C_ + c)) * NN + ig + iv0]       = oA;
                *(float4*)&out[((size_t)(b * C_ + c + 1)) * NN + ig + iv0]   = oB;
            }
    }
}

// ============================================================================
extern "C" void kernel_launch(void* const* d_in, const int* in_sizes, int n_in,
                              void* d_out, int out_size)
{
    const float* x  = (const float*)d_in[0];
    const float* Wq = (const float*)d_in[1];
    const float* bq = (const float*)d_in[2];
    const float* Wk = (const float*)d_in[3];
    const float* bk = (const float*)d_in[4];
    const float* Wv = (const float*)d_in[5];
    const float* bv = (const float*)d_in[6];
    float* out = (float*)d_out;

    const int qk_smem = (3 * 64 * 64 + 2 * 16 * 192) * (int)sizeof(float);  // 73728
    cudaFuncSetAttribute(qk_conv_kernel, cudaFuncAttributeMaxDynamicSharedMemorySize, qk_smem);
    cudaFuncSetAttribute(attn_kernel, cudaFuncAttributeMaxDynamicSharedMemorySize,
                         ATOT * (int)sizeof(float));                         // 102144

    qk_conv_kernel<<<dim3(2, HH, B_), 256, qk_smem>>>(x, Wq, bq, Wk, bk);
    v_gemm_kernel<<<dim3(NN / 128, C_ / 64, B_), 256>>>(x, Wv, bv);
    attn_kernel<<<dim3(NN / 64, B_), 256, ATOT * sizeof(float)>>>(out);
}

// round 4
// speedup vs baseline: 1.1531x; 1.0032x over previous
#include <cuda_runtime.h>

#define B_  4
#define C_  256
#define C8_ 32
#define HH  64
#define WW  64
#define NN  4096   // H*W

// ---- scratch (static device globals; no allocation allowed) ----
__device__ float g_q[B_ * C8_ * NN];          // [b][d][n]
__device__ float g_k[B_ * C8_ * NN];          // [b][d][n]
__device__ float g_v[(size_t)B_ * NN * C_];   // [b][n][c]

// ---- packed f32x2 helpers (sm_100+: doubles fp32 FMA throughput).
// NOTE: must use b64 ("l") operands, not f64 ("d") — ptxas rejects %fd here.
typedef unsigned long long u64;
__device__ __forceinline__ u64 ffma2(u64 a, u64 b, u64 c) {
    u64 r; asm("fma.rn.f32x2 %0, %1, %2, %3;" : "=l"(r) : "l"(a), "l"(b), "l"(c));
    return r;
}
__device__ __forceinline__ u64 fmul2(u64 a, u64 b) {
    u64 r; asm("mul.rn.f32x2 %0, %1, %2;" : "=l"(r) : "l"(a), "l"(b));
    return r;
}
__device__ __forceinline__ u64 dup2(float v) {
    u64 r; asm("mov.b64 %0, {%1, %1};" : "=l"(r) : "f"(v));
    return r;
}
__device__ __forceinline__ float2 unpk(u64 d) {
    float2 r; asm("mov.b64 {%0, %1}, %2;" : "=f"(r.x), "=f"(r.y) : "l"(d));
    return r;
}

// ============================================================================
// Kernel 1: q (1x3 conv) + k (3x1 conv).  grid (half, h, b) = (2, 64, 4).
// CTA computes 16 q-dims + 16 k-dims for one (b,h) row, chunking C by 64.
// smem: xs[3][64][64] (48KB) + staged weights (24KB) => occupancy 3.
// ============================================================================
__global__ __launch_bounds__(256) void qk_conv_kernel(
    const float* __restrict__ x,
    const float* __restrict__ Wq, const float* __restrict__ bq,
    const float* __restrict__ Wk, const float* __restrict__ bk)
{
    extern __shared__ float smqk[];
    float* xs = smqk;                 // [3][64][64]
    float* ws = smqk + 3 * 64 * 64;   // [2][16][192]  (q-then-k, [dim][c*3+tap])

    const int b    = blockIdx.z;
    const int h    = blockIdx.y;
    const int half = blockIdx.x;
    const int t    = threadIdx.x;
    const int g    = t >> 3;            // 0..31
    const int w0   = (t & 7) * 8;
    const bool isq = (g < 16);
    const int dl   = isq ? g : (g - 16);
    const int dg   = half * 16 + dl;    // global output dim 0..31

    float a8[8];
#pragma unroll
    for (int u = 0; u < 8; u++) a8[u] = 0.f;

    for (int cb = 0; cb < C_; cb += 64) {
        __syncthreads();
        // x rows h-1,h,h+1 for channels cb..cb+63  (3072 float4s)
        for (int idx = t; idx < 3 * 64 * 16; idx += 256) {
            const int r = idx >> 10, rem = idx & 1023;
            const int c = rem >> 4, wq = (rem & 15) << 2;
            const int hh = h - 1 + r;
            float4 v = make_float4(0.f, 0.f, 0.f, 0.f);
            if (hh >= 0 && hh < HH)
                v = *(const float4*)&x[((size_t)(b * C_ + cb + c) * HH + hh) * WW + wq];
            *(float4*)&xs[(r * 64 + c) * 64 + wq] = v;
        }
        // weights for this chunk: 2 * 16 dims * 192 floats (1536 float4s)
        for (int idx = t; idx < 2 * 16 * 48; idx += 256) {
            const int which = idx / 768, rem = idx - which * 768;
            const int dd = rem / 48, cq = (rem % 48) * 4;
            const float* Wsrc = which ? Wk : Wq;
            *(float4*)&ws[(which * 16 + dd) * 192 + cq] =
                *(const float4*)&Wsrc[(size_t)(half * 16 + dd) * 768 + cb * 3 + cq];
        }
        __syncthreads();

        const float* wrow = &ws[(isq ? dl : 16 + dl) * 192];
        if (isq) {
            for (int c = 0; c < 64; c++) {
                const float wf0 = wrow[c * 3 + 0], wf1 = wrow[c * 3 + 1], wf2 = wrow[c * 3 + 2];
                const float* x1 = &xs[(64 + c) * 64];
                float xr[10];
                xr[0] = (w0 == 0) ? 0.f : x1[w0 - 1];
                const float4 A = *(const float4*)&x1[w0];
                const float4 Bq = *(const float4*)&x1[w0 + 4];
                xr[1] = A.x; xr[2] = A.y; xr[3] = A.z; xr[4] = A.w;
                xr[5] = Bq.x; xr[6] = Bq.y; xr[7] = Bq.z; xr[8] = Bq.w;
                xr[9] = (w0 == 56) ? 0.f : x1[w0 + 8];
#pragma unroll
                for (int u = 0; u < 8; u++)
                    a8[u] += wf0 * xr[u] + wf1 * xr[u + 1] + wf2 * xr[u + 2];
            }
        } else {
            for (int c = 0; c < 64; c++) {
                const float wf0 = wrow[c * 3 + 0], wf1 = wrow[c * 3 + 1], wf2 = wrow[c * 3 + 2];
                const float4 r0a = *(const float4*)&xs[(0 * 64 + c) * 64 + w0];
                const float4 r0b = *(const float4*)&xs[(0 * 64 + c) * 64 + w0 + 4];
                const float4 r1a = *(const float4*)&xs[(1 * 64 + c) * 64 + w0];
                const float4 r1b = *(const float4*)&xs[(1 * 64 + c) * 64 + w0 + 4];
                const float4 r2a = *(const float4*)&xs[(2 * 64 + c) * 64 + w0];
                const float4 r2b = *(const float4*)&xs[(2 * 64 + c) * 64 + w0 + 4];
                const float r0[8] = {r0a.x, r0a.y, r0a.z, r0a.w, r0b.x, r0b.y, r0b.z, r0b.w};
                const float r1[8] = {r1a.x, r1a.y, r1a.z, r1a.w, r1b.x, r1b.y, r1b.z, r1b.w};
                const float r2[8] = {r2a.x, r2a.y, r2a.z, r2a.w, r2b.x, r2b.y, r2b.z, r2b.w};
#pragma unroll
                for (int u = 0; u < 8; u++)
                    a8[u] += wf0 * r0[u] + wf1 * r1[u] + wf2 * r2[u];
            }
        }
    }

    const float bias = isq ? bq[dg] : bk[dg];
    float* dst = isq ? g_q : g_k;
    const size_t base = ((size_t)(b * C8_ + dg)) * NN + h * WW + w0;
#pragma unroll
    for (int u = 0; u < 8; u++) dst[base + u] = a8[u] + bias;
}

// ============================================================================
// Kernel 2: v = Wv @ x + bv, written [b][n][c].  f32x2 inner loop.
// ============================================================================
__global__ __launch_bounds__(256) void v_gemm_kernel(
    const float* __restrict__ x, const float* __restrict__ Wv,
    const float* __restrict__ bv)
{
    __shared__ __align__(16) float Wt[32 * 68];    // [k][c]
    __shared__ __align__(16) float Xs[32 * 128];   // [k][n]
    const int n0  = blockIdx.x * 128;
    const int c0b = blockIdx.y * 64;
    const int b   = blockIdx.z;
    const int t   = threadIdx.x;
    const int n0t = (t >> 3) * 4;
    const int c0t = (t & 7) * 8;

    u64 acc2[4][4];   // [i][c-pair]
#pragma unroll
    for (int i = 0; i < 4; i++)
#pragma unroll
        for (int j = 0; j < 4; j++) acc2[i][j] = 0ull;

    for (int kk = 0; kk < C_; kk += 32) {
        __syncthreads();
#pragma unroll
        for (int r = 0; r < 4; r++) {
            const int idx4 = t + r * 256;
            const int row = idx4 >> 5, nq = (idx4 & 31) << 2;
            *(float4*)&Xs[row * 128 + nq] =
                *(const float4*)&x[((size_t)(b * C_ + kk + row)) * NN + n0 + nq];
        }
#pragma unroll
        for (int r = 0; r < 8; r++) {
            const int idx = t + r * 256;
            const int c = idx >> 5, k = idx & 31;
            Wt[k * 68 + c] = Wv[(size_t)(c0b + c) * C_ + kk + k];
        }
        __syncthreads();
#pragma unroll 8
        for (int k = 0; k < 32; k++) {
            const float4 xv = *(const float4*)&Xs[k * 128 + n0t];
            const ulonglong2 wA = *(const ulonglong2*)&Wt[k * 68 + c0t];
            const ulonglong2 wB = *(const ulonglong2*)&Wt[k * 68 + c0t + 4];
            const u64 xd0 = dup2(xv.x), xd1 = dup2(xv.y), xd2 = dup2(xv.z), xd3 = dup2(xv.w);
            acc2[0][0] = ffma2(xd0, wA.x, acc2[0][0]); acc2[0][1] = ffma2(xd0, wA.y, acc2[0][1]);
            acc2[0][2] = ffma2(xd0, wB.x, acc2[0][2]); acc2[0][3] = ffma2(xd0, wB.y, acc2[0][3]);
            acc2[1][0] = ffma2(xd1, wA.x, acc2[1][0]); acc2[1][1] = ffma2(xd1, wA.y, acc2[1][1]);
            acc2[1][2] = ffma2(xd1, wB.x, acc2[1][2]); acc2[1][3] = ffma2(xd1, wB.y, acc2[1][3]);
            acc2[2][0] = ffma2(xd2, wA.x, acc2[2][0]); acc2[2][1] = ffma2(xd2, wA.y, acc2[2][1]);
            acc2[2][2] = ffma2(xd2, wB.x, acc2[2][2]); acc2[2][3] = ffma2(xd2, wB.y, acc2[2][3]);
            acc2[3][0] = ffma2(xd3, wA.x, acc2[3][0]); acc2[3][1] = ffma2(xd3, wA.y, acc2[3][1]);
            acc2[3][2] = ffma2(xd3, wB.x, acc2[3][2]); acc2[3][3] = ffma2(xd3, wB.y, acc2[3][3]);
        }
    }
#pragma unroll
    for (int i = 0; i < 4; i++) {
        const int n = n0 + n0t + i;
#pragma unroll
        for (int jp = 0; jp < 4; jp++) {
            const float2 f = unpk(acc2[i][jp]);
            const int c = c0b + c0t + 2 * jp;
            g_v[((size_t)b * NN + n) * C_ + c]     = f.x + bv[c];
            g_v[((size_t)b * NN + n) * C_ + c + 1] = f.y + bv[c + 1];
        }
    }
}

// ============================================================================
// Kernel 3: flash attention, fp32 via f32x2 packed FMA.
// CTA = (b, 64-query block).  grid (64, 4) = 256 CTAs, 2 CTAs/SM.
// smem: qs[32][68], ks[32][72], S[64][72] ([j][i]), vs[64][256], al[64].
// ============================================================================
#define AQS 0
#define AKS 2176            // 32*68
#define ASS 4480            // + 32*72
#define AVS 9088            // + 64*72
#define AAL 25472           // + 64*256
#define ATOT 25536          // + 64   -> 102144 bytes

__global__ __launch_bounds__(256, 2) void attn_kernel(float* __restrict__ out)
{
    extern __shared__ __align__(16) float sm[];
    float* qs  = sm + AQS;   // [d][i] stride 68
    float* ks  = sm + AKS;   // [d][j] stride 72
    float* Ssm = sm + ASS;   // [j][i] stride 72
    float* vs  = sm + AVS;   // [j][c] stride 256
    float* al  = sm + AAL;   // [64]

    const int t  = threadIdx.x;
    const int b  = blockIdx.y;
    const int ig = blockIdx.x * 64;

    const int tq = t & 15, tj = t >> 4;
    const int i0  = tq * 4;           // QK: i group
    const int j0  = tj * 4;           // QK: j group
    const int iv0 = tj * 4;           // PV: i group
    const int cv0 = tq * 4;           // PV: c base (strided by 64)
    const int row = t >> 2, part = t & 3;   // softmax: 4 threads/row

    {   // q tile [32][64]
        const float* qsrc = g_q + (size_t)b * C8_ * NN + ig;
        for (int idx = t; idx < 32 * 64; idx += 256) {
            const int d = idx >> 6, i = idx & 63;
            qs[d * 68 + i] = qsrc[(size_t)d * NN + i];
        }
    }

    u64 acc2[4][4][2];   // [ii][cc][c-pair]
#pragma unroll
    for (int a = 0; a < 4; a++)
#pragma unroll
        for (int c = 0; c < 4; c++) { acc2[a][c][0] = 0ull; acc2[a][c][1] = 0ull; }
    float m_i = -1e30f, l_i = 0.f;

    for (int jt = 0; jt < 64; jt++) {
        const int jg = jt * 64;
        __syncthreads();
        {   // k tile [32][64]
            const float* ksrc = g_k + (size_t)b * C8_ * NN + jg;
            for (int idx = t; idx < 32 * 64; idx += 256) {
                const int d = idx >> 6, j = idx & 63;
                ks[d * 72 + j] = ksrc[(size_t)d * NN + j];
            }
        }
        {   // v tile [64][256]
            const float4* vsrc = (const float4*)(g_v + ((size_t)b * NN + jg) * C_);
            float4* vdst = (float4*)vs;
            for (int idx = t; idx < 4096; idx += 256) vdst[idx] = vsrc[idx];
        }
        __syncthreads();

        {   // QK: 4 i x 4 j per thread, packed along j
            u64 s2[4][2];
#pragma unroll
            for (int a = 0; a < 4; a++) { s2[a][0] = 0ull; s2[a][1] = 0ull; }
#pragma unroll 8
            for (int d = 0; d < 32; d++) {
                const float4     q4 = *(const float4*)&qs[d * 68 + i0];
                const ulonglong2 k2 = *(const ulonglong2*)&ks[d * 72 + j0];
                const u64 qd0 = dup2(q4.x), qd1 = dup2(q4.y);
                const u64 qd2 = dup2(q4.z), qd3 = dup2(q4.w);
                s2[0][0] = ffma2(qd0, k2.x, s2[0][0]); s2[0][1] = ffma2(qd0, k2.y, s2[0][1]);
                s2[1][0] = ffma2(qd1, k2.x, s2[1][0]); s2[1][1] = ffma2(qd1, k2.y, s2[1][1]);
                s2[2][0] = ffma2(qd2, k2.x, s2[2][0]); s2[2][1] = ffma2(qd2, k2.y, s2[2][1]);
                s2[3][0] = ffma2(qd3, k2.x, s2[3][0]); s2[3][1] = ffma2(qd3, k2.y, s2[3][1]);
            }
#pragma unroll
            for (int jp = 0; jp < 2; jp++) {
                const float2 a0 = unpk(s2[0][jp]), a1 = unpk(s2[1][jp]);
                const float2 a2 = unpk(s2[2][jp]), a3 = unpk(s2[3][jp]);
                *(float4*)&Ssm[(j0 + 2 * jp) * 72 + i0] =
                    make_float4(a0.x, a1.x, a2.x, a3.x);
                *(float4*)&Ssm[(j0 + 2 * jp + 1) * 72 + i0] =
                    make_float4(a0.y, a1.y, a2.y, a3.y);
            }
        }
        __syncthreads();

        {   // online softmax: 4 threads per row, 16 j each (j = part + jj*4)
            float mx = -1e30f;
#pragma unroll
            for (int jj = 0; jj < 16; jj++)
                mx = fmaxf(mx, Ssm[(part + jj * 4) * 72 + row]);
            mx = fmaxf(mx, __shfl_xor_sync(0xffffffffu, mx, 1));
            mx = fmaxf(mx, __shfl_xor_sync(0xffffffffu, mx, 2));
            const float mn = fmaxf(m_i, mx);
            const float aold = __expf(m_i - mn);
            float sum = 0.f;
#pragma unroll
            for (int jj = 0; jj < 16; jj++) {
                float* p = &Ssm[(part + jj * 4) * 72 + row];
                const float e = __expf(*p - mn);
                *p = e;
                sum += e;
            }
            sum += __shfl_xor_sync(0xffffffffu, sum, 1);
            sum += __shfl_xor_sync(0xffffffffu, sum, 2);
            l_i = l_i * aold + sum;
            m_i = mn;
            if (part == 0) al[row] = aold;
        }
        __syncthreads();

        {   // rescale + PV, packed along c
            const u64 a0 = dup2(al[iv0]),     a1 = dup2(al[iv0 + 1]);
            const u64 a2 = dup2(al[iv0 + 2]), a3 = dup2(al[iv0 + 3]);
#pragma unroll
            for (int cc = 0; cc < 4; cc++) {
                acc2[0][cc][0] = fmul2(acc2[0][cc][0], a0); acc2[0][cc][1] = fmul2(acc2[0][cc][1], a0);
                acc2[1][cc][0] = fmul2(acc2[1][cc][0], a1); acc2[1][cc][1] = fmul2(acc2[1][cc][1], a1);
                acc2[2][cc][0] = fmul2(acc2[2][cc][0], a2); acc2[2][cc][1] = fmul2(acc2[2][cc][1], a2);
                acc2[3][cc][0] = fmul2(acc2[3][cc][0], a3); acc2[3][cc][1] = fmul2(acc2[3][cc][1], a3);
            }
#pragma unroll 4
            for (int j = 0; j < 64; j++) {
                const float4 p4 = *(const float4*)&Ssm[j * 72 + iv0];
                const u64 p0 = dup2(p4.x), p1 = dup2(p4.y);
                const u64 p2 = dup2(p4.z), p3 = dup2(p4.w);
                const float* vrow = &vs[j * 256 + cv0];
#pragma unroll
                for (int cc = 0; cc < 4; cc++) {
                    const ulonglong2 v2 = *(const ulonglong2*)&vrow[cc * 64];
                    acc2[0][cc][0] = ffma2(p0, v2.x, acc2[0][cc][0]);
                    acc2[0][cc][1] = ffma2(p0, v2.y, acc2[0][cc][1]);
                    acc2[1][cc][0] = ffma2(p1, v2.x, acc2[1][cc][0]);
                    acc2[1][cc][1] = ffma2(p1, v2.y, acc2[1][cc][1]);
                    acc2[2][cc][0] = ffma2(p2, v2.x, acc2[2][cc][0]);
                    acc2[2][cc][1] = ffma2(p2, v2.y, acc2[2][cc][1]);
                    acc2[3][cc][0] = ffma2(p3, v2.x, acc2[3][cc][0]);
                    acc2[3][cc][1] = ffma2(p3, v2.y, acc2[3][cc][1]);
                }
            }
        }
    }

    __syncthreads();
    if (part == 0) al[row] = 1.f / l_i;
    __syncthreads();
    {
        const float l0 = al[iv0], l1 = al[iv0 + 1], l2 = al[iv0 + 2], l3 = al[iv0 + 3];
#pragma unroll
        for (int cc = 0; cc < 4; cc++)
#pragma unroll
            for (int cp = 0; cp < 2; cp++) {
                const float2 x0 = unpk(acc2[0][cc][cp]);
                const float2 x1 = unpk(acc2[1][cc][cp]);
                const float2 x2 = unpk(acc2[2][cc][cp]);
                const float2 x3 = unpk(acc2[3][cc][cp]);
                const int c = cv0 + cc * 64 + cp * 2;
                const float4 oA = make_float4(x0.x * l0, x1.x * l1, x2.x * l2, x3.x * l3);
                const float4 oB = make_float4(x0.y * l0, x1.y * l1, x2.y * l2, x3.y * l3);
                *(float4*)&out[((size_t)(b * C_ + c)) * NN + ig + iv0]       = oA;
                *(float4*)&out[((size_t)(b * C_ + c + 1)) * NN + ig + iv0]   = oB;
            }
    }
}

// ============================================================================
extern "C" void kernel_launch(void* const* d_in, const int* in_sizes, int n_in,
                              void* d_out, int out_size)
{
    const float* x  = (const float*)d_in[0];
    const float* Wq = (const float*)d_in[1];
    const float* bq = (const float*)d_in[2];
    const float* Wk = (const float*)d_in[3];
    const float* bk = (const float*)d_in[4];
    const float* Wv = (const float*)d_in[5];
    const float* bv = (const float*)d_in[6];
    float* out = (float*)d_out;

    const int qk_smem = (3 * 64 * 64 + 2 * 16 * 192) * (int)sizeof(float);  // 73728
    cudaFuncSetAttribute(qk_conv_kernel, cudaFuncAttributeMaxDynamicSharedMemorySize, qk_smem);
    cudaFuncSetAttribute(attn_kernel, cudaFuncAttributeMaxDynamicSharedMemorySize,
                         ATOT * (int)sizeof(float));                         // 102144

    qk_conv_kernel<<<dim3(2, HH, B_), 256, qk_smem>>>(x, Wq, bq, Wk, bk);
    v_gemm_kernel<<<dim3(NN / 128, C_ / 64, B_), 256>>>(x, Wv, bv);
    attn_kernel<<<dim3(NN / 64, B_), 256, ATOT * sizeof(float)>>>(out);
}

// round 9
// speedup vs baseline: 2.1742x; 1.8855x over previous
#include <cuda_runtime.h>
#include <cuda_bf16.h>
#include <cstdint>

#define B_  4
#define C_  256
#define HH  64
#define WW  64
#define NN  4096

// ---- scratch ----
__device__ __nv_bfloat16 g_qc[(size_t)B_ * NN * 64];  // [b][n][0:32 hi | 32:64 lo]
__device__ __nv_bfloat16 g_kc[(size_t)B_ * NN * 64];
__device__ __nv_bfloat16 g_vh[(size_t)B_ * NN * C_]; // [b][n][c] hi
__device__ __nv_bfloat16 g_vl[(size_t)B_ * NN * C_]; // [b][n][c] lo

typedef unsigned long long u64;
__device__ __forceinline__ u64 ffma2(u64 a, u64 b, u64 c) {
    u64 r; asm("fma.rn.f32x2 %0, %1, %2, %3;" : "=l"(r) : "l"(a), "l"(b), "l"(c));
    return r;
}
__device__ __forceinline__ u64 dup2(float v) {
    u64 r; asm("mov.b64 %0, {%1, %1};" : "=l"(r) : "f"(v));
    return r;
}
__device__ __forceinline__ float2 unpk(u64 d) {
    float2 r; asm("mov.b64 {%0, %1}, %2;" : "=f"(r.x), "=f"(r.y) : "l"(d));
    return r;
}

// ---- warp-MMA helpers (compute_100-baseline legal) ----
__device__ __forceinline__ uint32_t smem_u32(const void* p) {
    uint32_t a;
    asm("{ .reg .u64 t; cvta.to.shared.u64 t, %1; cvt.u32.u64 %0, t; }" : "=r"(a) : "l"(p));
    return a;
}
__device__ __forceinline__ void mma16816(float* d, const uint32_t* a, const uint32_t* b) {
    asm volatile(
        "mma.sync.aligned.m16n8k16.row.col.f32.bf16.bf16.f32 "
        "{%0,%1,%2,%3}, {%4,%5,%6,%7}, {%8,%9}, {%0,%1,%2,%3};"
        : "+f"(d[0]), "+f"(d[1]), "+f"(d[2]), "+f"(d[3])
        : "r"(a[0]), "r"(a[1]), "r"(a[2]), "r"(a[3]), "r"(b[0]), "r"(b[1]));
}
__device__ __forceinline__ void ldmx2(uint32_t* d, uint32_t addr) {
    asm volatile("ldmatrix.sync.aligned.m8n8.x2.shared.b16 {%0,%1}, [%2];"
                 : "=r"(d[0]), "=r"(d[1]) : "r"(addr));
}
__device__ __forceinline__ void ldmx2t(uint32_t* d, uint32_t addr) {
    asm volatile("ldmatrix.sync.aligned.m8n8.x2.trans.shared.b16 {%0,%1}, [%2];"
                 : "=r"(d[0]), "=r"(d[1]) : "r"(addr));
}
__device__ __forceinline__ void cpa16(uint32_t dst, const void* src) {
    asm volatile("cp.async.cg.shared.global [%0], [%1], 16;" :: "r"(dst), "l"(src));
}
__device__ __forceinline__ void cpa_commit() {
    asm volatile("cp.async.commit_group;" ::: "memory");
}
template<int N> __device__ __forceinline__ void cpa_wait() {
    asm volatile("cp.async.wait_group %0;" :: "n"(N) : "memory");
}
__device__ __forceinline__ uint32_t pack_bf16(float lo, float hi) {
    uint32_t r; asm("cvt.rn.bf16x2.f32 %0, %1, %2;" : "=r"(r) : "f"(hi), "f"(lo));
    return r;
}
__device__ __forceinline__ float fast_exp60(float s) {  // exp(s-60), FMA-pipe only
    float t = fmaxf(s - 60.f, -80.f) * 1.442695041f;
    float n = rintf(t);
    float f = t - n;
    float r = 1.3333558146e-3f;
    r = fmaf(r, f, 9.6181291208e-3f);
    r = fmaf(r, f, 5.5504108664e-2f);
    r = fmaf(r, f, 2.4022650696e-1f);
    r = fmaf(r, f, 6.9314718056e-1f);
    r = fmaf(r, f, 1.0f);
    return r * __int_as_float(((int)n + 127) << 23);
}

// ============================================================================
// Kernel 1: q (1x3) + k (3x1) convs -> bf16 hi/lo rows [b][n][64].
// ============================================================================
__global__ __launch_bounds__(256) void qk_conv_kernel(
    const float* __restrict__ x,
    const float* __restrict__ Wq, const float* __restrict__ bq,
    const float* __restrict__ Wk, const float* __restrict__ bk)
{
    extern __shared__ float smqk[];
    float* xs = smqk;
    float* ws = smqk + 3 * 64 * 64;

    const int b = blockIdx.z, h = blockIdx.y, half = blockIdx.x;
    const int t = threadIdx.x, g = t >> 3, w0 = (t & 7) * 8;
    const bool isq = (g < 16);
    const int dl = isq ? g : (g - 16);
    const int dg = half * 16 + dl;

    float a8[8];
#pragma unroll
    for (int u = 0; u < 8; u++) a8[u] = 0.f;

    for (int cb = 0; cb < C_; cb += 64) {
        __syncthreads();
        for (int idx = t; idx < 3 * 64 * 16; idx += 256) {
            const int r = idx >> 10, rem = idx & 1023;
            const int c = rem >> 4, wq = (rem & 15) << 2;
            const int hh = h - 1 + r;
            float4 v = make_float4(0.f, 0.f, 0.f, 0.f);
            if (hh >= 0 && hh < HH)
                v = *(const float4*)&x[((size_t)(b * C_ + cb + c) * HH + hh) * WW + wq];
            *(float4*)&xs[(r * 64 + c) * 64 + wq] = v;
        }
        for (int idx = t; idx < 2 * 16 * 48; idx += 256) {
            const int which = idx / 768, rem = idx - which * 768;
            const int dd = rem / 48, cq = (rem % 48) * 4;
            const float* Wsrc = which ? Wk : Wq;
            *(float4*)&ws[(which * 16 + dd) * 192 + cq] =
                *(const float4*)&Wsrc[(size_t)(half * 16 + dd) * 768 + cb * 3 + cq];
        }
        __syncthreads();

        const float* wrow = &ws[(isq ? dl : 16 + dl) * 192];
        if (isq) {
            for (int c = 0; c < 64; c++) {
                const float wf0 = wrow[c * 3], wf1 = wrow[c * 3 + 1], wf2 = wrow[c * 3 + 2];
                const float* x1 = &xs[(64 + c) * 64];
                float xr[10];
                xr[0] = (w0 == 0) ? 0.f : x1[w0 - 1];
                const float4 A = *(const float4*)&x1[w0];
                const float4 Bq = *(const float4*)&x1[w0 + 4];
                xr[1] = A.x; xr[2] = A.y; xr[3] = A.z; xr[4] = A.w;
                xr[5] = Bq.x; xr[6] = Bq.y; xr[7] = Bq.z; xr[8] = Bq.w;
                xr[9] = (w0 == 56) ? 0.f : x1[w0 + 8];
#pragma unroll
                for (int u = 0; u < 8; u++)
                    a8[u] += wf0 * xr[u] + wf1 * xr[u + 1] + wf2 * xr[u + 2];
            }
        } else {
            for (int c = 0; c < 64; c++) {
                const float wf0 = wrow[c * 3], wf1 = wrow[c * 3 + 1], wf2 = wrow[c * 3 + 2];
                const float4 r0a = *(const float4*)&xs[(0 * 64 + c) * 64 + w0];
                const float4 r0b = *(const float4*)&xs[(0 * 64 + c) * 64 + w0 + 4];
                const float4 r1a = *(const float4*)&xs[(1 * 64 + c) * 64 + w0];
                const float4 r1b = *(const float4*)&xs[(1 * 64 + c) * 64 + w0 + 4];
                const float4 r2a = *(const float4*)&xs[(2 * 64 + c) * 64 + w0];
                const float4 r2b = *(const float4*)&xs[(2 * 64 + c) * 64 + w0 + 4];
                const float r0[8] = {r0a.x, r0a.y, r0a.z, r0a.w, r0b.x, r0b.y, r0b.z, r0b.w};
                const float r1[8] = {r1a.x, r1a.y, r1a.z, r1a.w, r1b.x, r1b.y, r1b.z, r1b.w};
                const float r2[8] = {r2a.x, r2a.y, r2a.z, r2a.w, r2b.x, r2b.y, r2b.z, r2b.w};
#pragma unroll
                for (int u = 0; u < 8; u++)
                    a8[u] += wf0 * r0[u] + wf1 * r1[u] + wf2 * r2[u];
            }
        }
    }

    const float bias = isq ? bq[dg] : bk[dg];
    __nv_bfloat16* dst = isq ? g_qc : g_kc;
#pragma unroll
    for (int u = 0; u < 8; u++) {
        const int n = h * WW + w0 + u;
        const float val = a8[u] + bias;
        const __nv_bfloat16 hi = __float2bfloat16(val);
        const float lo = val - __bfloat162float(hi);
        dst[((size_t)b * NN + n) * 64 + dg]      = hi;
        dst[((size_t)b * NN + n) * 64 + 32 + dg] = __float2bfloat16(lo);
    }
}

// ============================================================================
// Kernel 2: v gemm -> bf16 hi/lo, [b][n][c].
// ============================================================================
__global__ __launch_bounds__(256) void v_gemm_kernel(
    const float* __restrict__ x, const float* __restrict__ Wv,
    const float* __restrict__ bv)
{
    __shared__ __align__(16) float Wt[32 * 68];
    __shared__ __align__(16) float Xs[32 * 128];
    const int n0 = blockIdx.x * 128, c0b = blockIdx.y * 64, b = blockIdx.z;
    const int t = threadIdx.x;
    const int n0t = (t >> 3) * 4, c0t = (t & 7) * 8;

    u64 acc2[4][4];
#pragma unroll
    for (int i = 0; i < 4; i++)
#pragma unroll
        for (int j = 0; j < 4; j++) acc2[i][j] = 0ull;

    for (int kk = 0; kk < C_; kk += 32) {
        __syncthreads();
#pragma unroll
        for (int r = 0; r < 4; r++) {
            const int idx4 = t + r * 256;
            const int row = idx4 >> 5, nq = (idx4 & 31) << 2;
            *(float4*)&Xs[row * 128 + nq] =
                *(const float4*)&x[((size_t)(b * C_ + kk + row)) * NN + n0 + nq];
        }
#pragma unroll
        for (int r = 0; r < 8; r++) {
            const int idx = t + r * 256;
            const int c = idx >> 5, k = idx & 31;
            Wt[k * 68 + c] = Wv[(size_t)(c0b + c) * C_ + kk + k];
        }
        __syncthreads();
#pragma unroll 8
        for (int k = 0; k < 32; k++) {
            const float4 xv = *(const float4*)&Xs[k * 128 + n0t];
            const ulonglong2 wA = *(const ulonglong2*)&Wt[k * 68 + c0t];
            const ulonglong2 wB = *(const ulonglong2*)&Wt[k * 68 + c0t + 4];
            const u64 x0 = dup2(xv.x), x1 = dup2(xv.y), x2 = dup2(xv.z), x3 = dup2(xv.w);
            acc2[0][0] = ffma2(x0, wA.x, acc2[0][0]); acc2[0][1] = ffma2(x0, wA.y, acc2[0][1]);
            acc2[0][2] = ffma2(x0, wB.x, acc2[0][2]); acc2[0][3] = ffma2(x0, wB.y, acc2[0][3]);
            acc2[1][0] = ffma2(x1, wA.x, acc2[1][0]); acc2[1][1] = ffma2(x1, wA.y, acc2[1][1]);
            acc2[1][2] = ffma2(x1, wB.x, acc2[1][2]); acc2[1][3] = ffma2(x1, wB.y, acc2[1][3]);
            acc2[2][0] = ffma2(x2, wA.x, acc2[2][0]); acc2[2][1] = ffma2(x2, wA.y, acc2[2][1]);
            acc2[2][2] = ffma2(x2, wB.x, acc2[2][2]); acc2[2][3] = ffma2(x2, wB.y, acc2[2][3]);
            acc2[3][0] = ffma2(x3, wA.x, acc2[3][0]); acc2[3][1] = ffma2(x3, wA.y, acc2[3][1]);
            acc2[3][2] = ffma2(x3, wB.x, acc2[3][2]); acc2[3][3] = ffma2(x3, wB.y, acc2[3][3]);
        }
    }
#pragma unroll
    for (int i = 0; i < 4; i++) {
        const int n = n0 + n0t + i;
#pragma unroll
        for (int jp = 0; jp < 4; jp++) {
            const float2 f = unpk(acc2[i][jp]);
            const int c = c0b + c0t + 2 * jp;
            const float v0 = f.x + bv[c], v1 = f.y + bv[c + 1];
            const __nv_bfloat16 h0 = __float2bfloat16(v0), h1 = __float2bfloat16(v1);
            const size_t base = ((size_t)b * NN + n) * C_ + c;
            g_vh[base]     = h0;
            g_vh[base + 1] = h1;
            g_vl[base]     = __float2bfloat16(v0 - __bfloat162float(h0));
            g_vl[base + 1] = __float2bfloat16(v1 - __bfloat162float(h1));
        }
    }
}

// ============================================================================
// Kernel 3: warp-MMA flash attention (bf16 hi/lo, no-rescale softmax).
// CTA = 128 queries, 8 warps = 4 row-groups x 2 c-halves. 64-key tiles,
// cp.async double buffered. P stays in registers (C->A fragment identity).
// smem per buf: K 8KB | Vh 32KB | Vl 32KB = 72KB; x2 = 147456 B.
// ============================================================================
#define SM_BUF 73728
#define SM_ATT (2 * SM_BUF)

__global__ __launch_bounds__(256, 1) void attn_kernel(float* __restrict__ out)
{
    extern __shared__ __align__(16) char smem[];
    const uint32_t sb = smem_u32(smem);

    const int t = threadIdx.x, w = t >> 5, lane = t & 31;
    const int b = blockIdx.y, ig = blockIdx.x * 128;
    const int rg = w >> 1, ch = w & 1;
    const int i0 = rg * 32, c0 = ch * 128;
    const int g = lane >> 2, qp = (lane & 3) * 2;

    // ---- load Q fragments (persistent in registers) ----
    uint32_t qa[2][4][4];
#pragma unroll
    for (int mt = 0; mt < 2; mt++)
#pragma unroll
        for (int kc = 0; kc < 4; kc++) {
            const size_t r0 = (size_t)b * NN + ig + i0 + mt * 16 + g;
            const int col = kc * 16 + qp;
            qa[mt][kc][0] = *(const uint32_t*)&g_qc[r0 * 64 + col];
            qa[mt][kc][1] = *(const uint32_t*)&g_qc[(r0 + 8) * 64 + col];
            qa[mt][kc][2] = *(const uint32_t*)&g_qc[r0 * 64 + col + 8];
            qa[mt][kc][3] = *(const uint32_t*)&g_qc[(r0 + 8) * 64 + col + 8];
        }

    float O[2][16][4];
#pragma unroll
    for (int mt = 0; mt < 2; mt++)
#pragma unroll
        for (int cn = 0; cn < 16; cn++)
#pragma unroll
            for (int r = 0; r < 4; r++) O[mt][cn][r] = 0.f;
    float sums[2][2] = {{0.f, 0.f}, {0.f, 0.f}};

    // ---- tile loader (cp.async, swizzled) ----
    auto load_tile = [&](int jtile, int buf) {
        const uint32_t base = sb + buf * SM_BUF;
        const char* ksrc = (const char*)(g_kc + ((size_t)b * NN + jtile * 64) * 64);
        for (int idx = t; idx < 512; idx += 256) {
            const int j = idx >> 3, c = idx & 7;
            cpa16(base + j * 128 + ((c ^ (j & 7)) << 4), ksrc + j * 128 + c * 16);
        }
        const char* vhs = (const char*)(g_vh + ((size_t)b * NN + jtile * 64) * C_);
        const char* vls = (const char*)(g_vl + ((size_t)b * NN + jtile * 64) * C_);
        for (int idx = t; idx < 2048; idx += 256) {
            const int j = idx >> 5, c = idx & 31;
            const uint32_t dst = j * 512 + ((c ^ (j & 7)) << 4);
            cpa16(base + 8192 + dst, vhs + j * 512 + c * 16);
            cpa16(base + 40960 + dst, vls + j * 512 + c * 16);
        }
    };

    load_tile(0, 0);
    cpa_commit();

    for (int jt = 0; jt < 64; jt++) {
        const int buf = jt & 1;
        if (jt + 1 < 64) {
            load_tile(jt + 1, buf ^ 1);
            cpa_commit();
            cpa_wait<1>();
        } else {
            cpa_wait<0>();
        }
        __syncthreads();

        const uint32_t KS = sb + buf * SM_BUF;
        const uint32_t VH = KS + 8192, VL = KS + 40960;

#pragma unroll 1
        for (int jc = 0; jc < 4; jc++) {
            // ---- QK: S[16|16 rows][16 j] per mt ----
            float S[2][2][4];
#pragma unroll
            for (int mt = 0; mt < 2; mt++)
#pragma unroll
                for (int jn = 0; jn < 2; jn++)
#pragma unroll
                    for (int r = 0; r < 4; r++) S[mt][jn][r] = 0.f;

#pragma unroll
            for (int jn = 0; jn < 2; jn++) {
                const int jb = jc * 16 + jn * 8;
                uint32_t kb[4][2];
#pragma unroll
                for (int kd = 0; kd < 4; kd++) {
                    const int row = jb + (lane & 7);
                    const int chunk = kd * 2 + ((lane >> 3) & 1);
                    ldmx2(kb[kd], KS + row * 128 + ((chunk ^ (row & 7)) << 4));
                }
#pragma unroll
                for (int mt = 0; mt < 2; mt++) {
                    mma16816(S[mt][jn], qa[mt][0], kb[0]);  // qh*kh
                    mma16816(S[mt][jn], qa[mt][1], kb[1]);
                    mma16816(S[mt][jn], qa[mt][2], kb[0]);  // ql*kh
                    mma16816(S[mt][jn], qa[mt][3], kb[1]);
                    mma16816(S[mt][jn], qa[mt][0], kb[2]);  // qh*kl
                    mma16816(S[mt][jn], qa[mt][1], kb[3]);
                }
            }

            // ---- softmax (register-resident) + P hi/lo A-fragments ----
            uint32_t pha[2][4], pla[2][4];
#pragma unroll
            for (int mt = 0; mt < 2; mt++) {
#pragma unroll
                for (int jn = 0; jn < 2; jn++) {
                    const float e0 = fast_exp60(S[mt][jn][0]);
                    const float e1 = fast_exp60(S[mt][jn][1]);
                    const float e2 = fast_exp60(S[mt][jn][2]);
                    const float e3 = fast_exp60(S[mt][jn][3]);
                    sums[mt][0] += e0 + e1;
                    sums[mt][1] += e2 + e3;
                    const uint32_t h01 = pack_bf16(e0, e1);
                    const uint32_t h23 = pack_bf16(e2, e3);
                    pha[mt][jn * 2]     = h01;   // a0/a2
                    pha[mt][jn * 2 + 1] = h23;   // a1/a3
                    pla[mt][jn * 2] = pack_bf16(
                        e0 - __uint_as_float(h01 << 16),
                        e1 - __uint_as_float(h01 & 0xffff0000u));
                    pla[mt][jn * 2 + 1] = pack_bf16(
                        e2 - __uint_as_float(h23 << 16),
                        e3 - __uint_as_float(h23 & 0xffff0000u));
                }
            }

            // ---- PV: O += P * V (3 terms) ----
            const int vrow = jc * 16 + (lane & 15);
#pragma unroll
            for (int cn = 0; cn < 16; cn++) {
                const int cb16 = (c0 >> 3) + cn;
                const uint32_t voff = vrow * 512 + ((cb16 ^ (vrow & 7)) << 4);
                uint32_t vhb[2], vlb[2];
                ldmx2t(vhb, VH + voff);
                ldmx2t(vlb, VL + voff);
#pragma unroll
                for (int mt = 0; mt < 2; mt++) {
                    mma16816(O[mt][cn], pha[mt], vhb);
                    mma16816(O[mt][cn], pla[mt], vhb);
                    mma16816(O[mt][cn], pha[mt], vlb);
                }
            }
        }
        __syncthreads();
    }

    // ---- rowsum reduce (4 lanes share a row) + store ----
    float inv[2][2];
#pragma unroll
    for (int mt = 0; mt < 2; mt++)
#pragma unroll
        for (int hh = 0; hh < 2; hh++) {
            float s = sums[mt][hh];
            s += __shfl_xor_sync(0xffffffffu, s, 1);
            s += __shfl_xor_sync(0xffffffffu, s, 2);
            inv[mt][hh] = 1.f / s;
        }

#pragma unroll
    for (int mt = 0; mt < 2; mt++) {
        const int r0 = ig + i0 + mt * 16 + g, r1 = r0 + 8;
#pragma unroll
        for (int cn = 0; cn < 16; cn++) {
            const int c = c0 + cn * 8 + qp;
            out[((size_t)(b * C_ + c)) * NN + r0]     = O[mt][cn][0] * inv[mt][0];
            out[((size_t)(b * C_ + c + 1)) * NN + r0] = O[mt][cn][1] * inv[mt][0];
            out[((size_t)(b * C_ + c)) * NN + r1]     = O[mt][cn][2] * inv[mt][1];
            out[((size_t)(b * C_ + c + 1)) * NN + r1] = O[mt][cn][3] * inv[mt][1];
        }
    }
}

// ============================================================================
extern "C" void kernel_launch(void* const* d_in, const int* in_sizes, int n_in,
                              void* d_out, int out_size)
{
    const float* x  = (const float*)d_in[0];
    const float* Wq = (const float*)d_in[1];
    const float* bq = (const float*)d_in[2];
    const float* Wk = (const float*)d_in[3];
    const float* bk = (const float*)d_in[4];
    const float* Wv = (const float*)d_in[5];
    const float* bv = (const float*)d_in[6];
    float* out = (float*)d_out;

    const int qk_smem = (3 * 64 * 64 + 2 * 16 * 192) * (int)sizeof(float);
    cudaFuncSetAttribute(qk_conv_kernel, cudaFuncAttributeMaxDynamicSharedMemorySize, qk_smem);
    cudaFuncSetAttribute(attn_kernel, cudaFuncAttributeMaxDynamicSharedMemorySize, SM_ATT);

    qk_conv_kernel<<<dim3(2, HH, B_), 256, qk_smem>>>(x, Wq, bq, Wk, bk);
    v_gemm_kernel<<<dim3(NN / 128, C_ / 64, B_), 256>>>(x, Wv, bv);
    attn_kernel<<<dim3(NN / 128, B_), 256, SM_ATT>>>(out);
}